// round 1
// baseline (speedup 1.0000x reference)
#include <cuda_runtime.h>
#include <math.h>

#define B_   2
#define S_   2048
#define HID_ 2048
#define H_   16
#define HS_  128
#define RD_  32

// ---------------- scratch (device globals; no allocation in kernel_launch) ----------------
__device__ float g_qkv[(size_t)B_ * S_ * 3 * HID_];     // [4096, 6144] raw qkv
__device__ float g_Q[(size_t)B_ * H_ * S_ * HS_];       // [B,H,S,HS]
__device__ float g_K[(size_t)B_ * H_ * S_ * HS_];
__device__ float g_V[(size_t)B_ * H_ * S_ * HS_];
__device__ float g_att[(size_t)B_ * S_ * HID_];         // [4096, 2048] attn out (B,S,H*HS)

// ---------------- SGEMM: C[M,N] = A[M,K] @ B[K,N] + bias[N] ----------------
// 128x128 block tile, BK=16, 256 threads, 8x8 per-thread microtile.
__global__ __launch_bounds__(256) void sgemm_bias(
    const float* __restrict__ A, const float* __restrict__ Bm,
    const float* __restrict__ bias, float* __restrict__ C,
    int M, int N, int K)
{
    __shared__ float As[16][128];   // [k][m] (transposed A tile)
    __shared__ float Bs[16][128];   // [k][n]

    const int t = threadIdx.x;
    const int brow = blockIdx.y * 128;
    const int bcol = blockIdx.x * 128;
    const int ty = t >> 4;          // 0..15
    const int tx = t & 15;          // 0..15

    float acc[8][8];
#pragma unroll
    for (int i = 0; i < 8; i++)
#pragma unroll
        for (int j = 0; j < 8; j++) acc[i][j] = 0.f;

    for (int k0 = 0; k0 < K; k0 += 16) {
#pragma unroll
        for (int i = 0; i < 2; i++) {
            int f = t + i * 256;                 // 0..511 float4 index
            int ar = f >> 2;                     // 0..127
            int ac = (f & 3) << 2;               // 0,4,8,12
            float4 va = *(const float4*)(A + (size_t)(brow + ar) * K + k0 + ac);
            As[ac + 0][ar] = va.x;
            As[ac + 1][ar] = va.y;
            As[ac + 2][ar] = va.z;
            As[ac + 3][ar] = va.w;
            int br = f >> 5;                     // 0..15
            int bc = (f & 31) << 2;              // 0..124
            *(float4*)(&Bs[br][bc]) = *(const float4*)(Bm + (size_t)(k0 + br) * N + bcol + bc);
        }
        __syncthreads();

#pragma unroll
        for (int k = 0; k < 16; k++) {
            float a[8], bb[8];
            *(float4*)&a[0]  = *(float4*)&As[k][ty * 8];
            *(float4*)&a[4]  = *(float4*)&As[k][ty * 8 + 4];
            *(float4*)&bb[0] = *(float4*)&Bs[k][tx * 8];
            *(float4*)&bb[4] = *(float4*)&Bs[k][tx * 8 + 4];
#pragma unroll
            for (int i = 0; i < 8; i++)
#pragma unroll
                for (int j = 0; j < 8; j++)
                    acc[i][j] = fmaf(a[i], bb[j], acc[i][j]);
        }
        __syncthreads();
    }

#pragma unroll
    for (int i = 0; i < 8; i++) {
        int row = brow + ty * 8 + i;
#pragma unroll
        for (int j = 0; j < 8; j += 4) {
            int col = bcol + tx * 8 + j;
            float4 o;
            o.x = acc[i][j + 0] + bias[col + 0];
            o.y = acc[i][j + 1] + bias[col + 1];
            o.z = acc[i][j + 2] + bias[col + 2];
            o.w = acc[i][j + 3] + bias[col + 3];
            *(float4*)(C + (size_t)row * N + col) = o;
        }
    }
}

// ---------------- rotary + scatter to [B,H,S,HS] ----------------
__global__ __launch_bounds__(256) void rotary_scatter(
    const float* __restrict__ qkv, const int* __restrict__ pos,
    float* __restrict__ Q, float* __restrict__ K, float* __restrict__ V)
{
    int idx = blockIdx.x * 256 + threadIdx.x;      // over B*S*H*HS = 8388608
    int d = idx & 127;
    int h = (idx >> 7) & 15;
    int s = (idx >> 11) & (S_ - 1);
    int b = idx >> 22;

    const float* base = qkv + (size_t)(b * S_ + s) * (3 * HID_) + h * (3 * HS_);
    float q = base[d];
    float k = base[HS_ + d];
    float v = base[2 * HS_ + d];

    if (d < RD_) {
        float p = (float)pos[b * S_ + s];
        int i = d & 15;
        // inv_freq = 10000^(-2i/RD)
        float f = p * expf((float)(2 * i) * (-1.0f / (float)RD_) * 9.210340371976184f);
        float c = cosf(f);
        float sn = sinf(f);
        int pd = (d < 16) ? d + 16 : d - 16;
        float sgn = (d < 16) ? -1.f : 1.f;
        float qp = base[pd];
        float kp = base[HS_ + pd];
        q = q * c + sgn * qp * sn;
        k = k * c + sgn * kp * sn;
    }
    size_t oi = ((size_t)(b * H_ + h) * S_ + s) * HS_ + d;
    Q[oi] = q;
    K[oi] = k;
    V[oi] = v;
}

// ---------------- flash attention (causal), fp32 ----------------
// Block: 256 threads handles one (b, h, 64-row q tile). Key tiles of 64.
// smem: Qs[128][68] + Ks[128][68] (transposed, padded) + Vs[64][128] + Ps[64][64] + stats
#define FA_SMEM_FLOATS (128*68 + 128*68 + 64*128 + 64*64 + 192)
#define FA_SMEM_BYTES  (FA_SMEM_FLOATS * 4)

__global__ __launch_bounds__(256) void flash_attn(
    const float* __restrict__ Q, const float* __restrict__ Kg,
    const float* __restrict__ V, const float* __restrict__ amask,
    float* __restrict__ Out)
{
    extern __shared__ float sm[];
    float* Qs = sm;                    // [128][68], Qs[d*68 + r]
    float* Ks = Qs + 128 * 68;         // [128][68]
    float* Vs = Ks + 128 * 68;         // [64][128], Vs[c*128 + d]
    float* Ps = Vs + 64 * 128;         // [64][64]
    float* m_s  = Ps + 64 * 64;        // [64]
    float* l_s  = m_s + 64;            // [64]
    float* sc_s = l_s + 64;            // [64]

    const int t = threadIdx.x;
    const int qt = blockIdx.x;
    const int h  = blockIdx.y;
    const int b  = blockIdx.z;
    const int q0 = qt * 64;
    const size_t bh = ((size_t)(b * H_ + h)) * S_ * HS_;

    // Load Q tile transposed
#pragma unroll
    for (int i = 0; i < 8; i++) {
        int f = t + i * 256;            // 0..2047 float4
        int r = f >> 5;                 // 0..63
        int d = (f & 31) << 2;          // 0..124
        float4 v4 = *(const float4*)(Q + bh + (size_t)(q0 + r) * HS_ + d);
        Qs[(d + 0) * 68 + r] = v4.x;
        Qs[(d + 1) * 68 + r] = v4.y;
        Qs[(d + 2) * 68 + r] = v4.z;
        Qs[(d + 3) * 68 + r] = v4.w;
    }
    if (t < 64) { m_s[t] = -1e30f; l_s[t] = 0.f; }

    float o[8][4];
#pragma unroll
    for (int i = 0; i < 8; i++)
#pragma unroll
        for (int j = 0; j < 4; j++) o[i][j] = 0.f;

    const int rA = (t >> 4) * 4;   // score mapping: 4 rows
    const int cA = (t & 15) * 4;   //                4 cols
    const int rB = (t >> 5) * 8;   // output mapping: 8 rows
    const int cB = (t & 31) * 4;   //                 4 cols (of 128)

    const float scale = 0.08838834764831845f;  // 1/sqrt(128)

    for (int kt = 0; kt <= qt; kt++) {
        const int k0 = kt * 64;
        __syncthreads();   // protect Ks/Vs/Ps from previous iteration consumers

        // Load K tile transposed + V tile row-major
#pragma unroll
        for (int i = 0; i < 8; i++) {
            int f = t + i * 256;
            int r = f >> 5;
            int d = (f & 31) << 2;
            float4 kv = *(const float4*)(Kg + bh + (size_t)(k0 + r) * HS_ + d);
            Ks[(d + 0) * 68 + r] = kv.x;
            Ks[(d + 1) * 68 + r] = kv.y;
            Ks[(d + 2) * 68 + r] = kv.z;
            Ks[(d + 3) * 68 + r] = kv.w;
            *(float4*)(Vs + r * 128 + d) = *(const float4*)(V + bh + (size_t)(k0 + r) * HS_ + d);
        }
        __syncthreads();

        // S = Q K^T
        float s4[4][4];
#pragma unroll
        for (int i = 0; i < 4; i++)
#pragma unroll
            for (int j = 0; j < 4; j++) s4[i][j] = 0.f;

#pragma unroll 4
        for (int d = 0; d < 128; d++) {
            float4 qa = *(float4*)(Qs + d * 68 + rA);
            float4 kb = *(float4*)(Ks + d * 68 + cA);
            float a0 = qa.x, a1 = qa.y, a2 = qa.z, a3 = qa.w;
            float b0 = kb.x, b1 = kb.y, b2 = kb.z, b3 = kb.w;
            s4[0][0] = fmaf(a0, b0, s4[0][0]); s4[0][1] = fmaf(a0, b1, s4[0][1]);
            s4[0][2] = fmaf(a0, b2, s4[0][2]); s4[0][3] = fmaf(a0, b3, s4[0][3]);
            s4[1][0] = fmaf(a1, b0, s4[1][0]); s4[1][1] = fmaf(a1, b1, s4[1][1]);
            s4[1][2] = fmaf(a1, b2, s4[1][2]); s4[1][3] = fmaf(a1, b3, s4[1][3]);
            s4[2][0] = fmaf(a2, b0, s4[2][0]); s4[2][1] = fmaf(a2, b1, s4[2][1]);
            s4[2][2] = fmaf(a2, b2, s4[2][2]); s4[2][3] = fmaf(a2, b3, s4[2][3]);
            s4[3][0] = fmaf(a3, b0, s4[3][0]); s4[3][1] = fmaf(a3, b1, s4[3][1]);
            s4[3][2] = fmaf(a3, b2, s4[3][2]); s4[3][3] = fmaf(a3, b3, s4[3][3]);
        }

        // scale, causal mask, attention_mask, online softmax stats
        float mold[4], mnew[4], psum[4];
#pragma unroll
        for (int i = 0; i < 4; i++) {
            int qrow = q0 + rA + i;
            float mm = -1e30f;
#pragma unroll
            for (int j = 0; j < 4; j++) {
                int kcol = k0 + cA + j;
                float v = (kcol <= qrow) ? (s4[i][j] * scale + amask[(size_t)b * S_ + kcol]) : -1e30f;
                s4[i][j] = v;
                mm = fmaxf(mm, v);
            }
#pragma unroll
            for (int off = 1; off < 16; off <<= 1)
                mm = fmaxf(mm, __shfl_xor_sync(0xffffffffu, mm, off));
            mold[i] = m_s[rA + i];
            mnew[i] = fmaxf(mold[i], mm);
            float ps = 0.f;
#pragma unroll
            for (int j = 0; j < 4; j++) {
                float p = __expf(s4[i][j] - mnew[i]);
                s4[i][j] = p;
                ps += p;
            }
#pragma unroll
            for (int off = 1; off < 16; off <<= 1)
                ps += __shfl_xor_sync(0xffffffffu, ps, off);
            psum[i] = ps;
        }
        if ((t & 15) == 0) {
#pragma unroll
            for (int i = 0; i < 4; i++) {
                float scl = __expf(mold[i] - mnew[i]);
                sc_s[rA + i] = scl;
                l_s[rA + i] = l_s[rA + i] * scl + psum[i];
                m_s[rA + i] = mnew[i];
            }
        }
#pragma unroll
        for (int i = 0; i < 4; i++)
            *(float4*)(Ps + (rA + i) * 64 + cA) =
                make_float4(s4[i][0], s4[i][1], s4[i][2], s4[i][3]);
        __syncthreads();

        // O = O * rescale + P @ V
#pragma unroll
        for (int i = 0; i < 8; i++) {
            float f = sc_s[rB + i];
            o[i][0] *= f; o[i][1] *= f; o[i][2] *= f; o[i][3] *= f;
        }
#pragma unroll 2
        for (int c = 0; c < 64; c++) {
            float4 vv = *(float4*)(Vs + c * 128 + cB);
#pragma unroll
            for (int i = 0; i < 8; i++) {
                float p = Ps[(rB + i) * 64 + c];
                o[i][0] = fmaf(p, vv.x, o[i][0]);
                o[i][1] = fmaf(p, vv.y, o[i][1]);
                o[i][2] = fmaf(p, vv.z, o[i][2]);
                o[i][3] = fmaf(p, vv.w, o[i][3]);
            }
        }
    }

    // epilogue: normalize and store in [B,S,H*HS] layout
#pragma unroll
    for (int i = 0; i < 8; i++) {
        float rl = 1.0f / l_s[rB + i];
        float4 ov = make_float4(o[i][0] * rl, o[i][1] * rl, o[i][2] * rl, o[i][3] * rl);
        *(float4*)(Out + ((size_t)(b * S_ + q0 + rB + i)) * HID_ + h * HS_ + cB) = ov;
    }
}

// ---------------- launch ----------------
extern "C" void kernel_launch(void* const* d_in, const int* in_sizes, int n_in,
                              void* d_out, int out_size) {
    const float* hidden = (const float*)d_in[0];
    const float* amask  = (const float*)d_in[1];
    const int*   pos    = (const int*)d_in[2];
    const float* Wqkv   = (const float*)d_in[3];
    const float* bqkv   = (const float*)d_in[4];
    const float* Wd     = (const float*)d_in[5];
    const float* bd     = (const float*)d_in[6];
    float* out = (float*)d_out;

    float *qkv, *Qp, *Kp, *Vp, *att;
    cudaGetSymbolAddress((void**)&qkv, g_qkv);
    cudaGetSymbolAddress((void**)&Qp,  g_Q);
    cudaGetSymbolAddress((void**)&Kp,  g_K);
    cudaGetSymbolAddress((void**)&Vp,  g_V);
    cudaGetSymbolAddress((void**)&att, g_att);

    cudaFuncSetAttribute(flash_attn, cudaFuncAttributeMaxDynamicSharedMemorySize, FA_SMEM_BYTES);

    // 1) QKV GEMM + bias: [4096,2048]@[2048,6144]
    sgemm_bias<<<dim3(6144 / 128, 4096 / 128), 256>>>(hidden, Wqkv, bqkv, qkv, 4096, 6144, 2048);

    // 2) rotary + transpose scatter
    rotary_scatter<<<(B_ * S_ * H_ * HS_) / 256, 256>>>(qkv, pos, Qp, Kp, Vp);

    // 3) causal flash attention
    flash_attn<<<dim3(S_ / 64, H_, B_), 256, FA_SMEM_BYTES>>>(Qp, Kp, Vp, amask, att);

    // 4) dense GEMM + bias: [4096,2048]@[2048,2048]
    sgemm_bias<<<dim3(2048 / 128, 4096 / 128), 256>>>(att, Wd, bd, out, 4096, 2048, 2048);
}

// round 4
// speedup vs baseline: 1.7661x; 1.7661x over previous
#include <cuda_runtime.h>
#include <cuda_bf16.h>
#include <math.h>
#include <stdint.h>
#include <stddef.h>

#define B_   2
#define S_   2048
#define HID_ 2048
#define H_   16
#define HS_  128
#define RD_  32

// ---------------- scratch (device globals) ----------------
__device__ float g_qkv[(size_t)B_ * S_ * 3 * HID_];     // [4096, 6144] raw qkv
__device__ float g_Q[(size_t)B_ * H_ * S_ * HS_];       // [B,H,S,HS]
__device__ float g_K[(size_t)B_ * H_ * S_ * HS_];
__device__ float g_V[(size_t)B_ * H_ * S_ * HS_];

// bf16 split buffers
__device__ __nv_bfloat16 g_Ahi[(size_t)B_ * S_ * HID_];
__device__ __nv_bfloat16 g_Alo[(size_t)B_ * S_ * HID_];
__device__ __nv_bfloat16 g_Wqhi[(size_t)HID_ * 3 * HID_];
__device__ __nv_bfloat16 g_Wqlo[(size_t)HID_ * 3 * HID_];
__device__ __nv_bfloat16 g_Wdhi[(size_t)HID_ * HID_];
__device__ __nv_bfloat16 g_Wdlo[(size_t)HID_ * HID_];
__device__ __nv_bfloat16 g_Atthi[(size_t)B_ * S_ * HID_];
__device__ __nv_bfloat16 g_Attlo[(size_t)B_ * S_ * HID_];

// ---------------- PTX helpers ----------------
__device__ __forceinline__ unsigned smem_u32(const void* p) {
    return (unsigned)__cvta_generic_to_shared(p);
}
__device__ __forceinline__ void cp16(unsigned s, const void* g) {
    asm volatile("cp.async.cg.shared.global [%0], [%1], 16;" :: "r"(s), "l"(g));
}
__device__ __forceinline__ void cp_commit() {
    asm volatile("cp.async.commit_group;");
}
__device__ __forceinline__ void cp_wait_1() {
    asm volatile("cp.async.wait_group 1;");
}
__device__ __forceinline__ void cp_wait_0() {
    asm volatile("cp.async.wait_group 0;");
}
__device__ __forceinline__ void ldm4(unsigned* r, unsigned a) {
    asm volatile("ldmatrix.sync.aligned.m8n8.x4.shared.b16 {%0,%1,%2,%3}, [%4];"
        : "=r"(r[0]), "=r"(r[1]), "=r"(r[2]), "=r"(r[3]) : "r"(a));
}
__device__ __forceinline__ void ldm4t(unsigned* r, unsigned a) {
    asm volatile("ldmatrix.sync.aligned.m8n8.x4.trans.shared.b16 {%0,%1,%2,%3}, [%4];"
        : "=r"(r[0]), "=r"(r[1]), "=r"(r[2]), "=r"(r[3]) : "r"(a));
}
__device__ __forceinline__ void mma16816(float* d, const unsigned* a, const unsigned* b) {
    asm volatile(
        "mma.sync.aligned.m16n8k16.row.col.f32.bf16.bf16.f32 "
        "{%0,%1,%2,%3},{%4,%5,%6,%7},{%8,%9},{%0,%1,%2,%3};"
        : "+f"(d[0]), "+f"(d[1]), "+f"(d[2]), "+f"(d[3])
        : "r"(a[0]), "r"(a[1]), "r"(a[2]), "r"(a[3]), "r"(b[0]), "r"(b[1]));
}

// ---------------- bf16 split conversion ----------------
__global__ __launch_bounds__(256) void split_bf16(
    const float* __restrict__ x, __nv_bfloat16* __restrict__ hi,
    __nv_bfloat16* __restrict__ lo, int n4)
{
    int i = blockIdx.x * 256 + threadIdx.x;
    if (i >= n4) return;
    float4 v = ((const float4*)x)[i];
    __nv_bfloat16 h0 = __float2bfloat16(v.x);
    __nv_bfloat16 h1 = __float2bfloat16(v.y);
    __nv_bfloat16 h2 = __float2bfloat16(v.z);
    __nv_bfloat16 h3 = __float2bfloat16(v.w);
    __nv_bfloat162 ph0; ph0.x = h0; ph0.y = h1;
    __nv_bfloat162 ph1; ph1.x = h2; ph1.y = h3;
    __nv_bfloat162 pl0, pl1;
    pl0.x = __float2bfloat16(v.x - __bfloat162float(h0));
    pl0.y = __float2bfloat16(v.y - __bfloat162float(h1));
    pl1.x = __float2bfloat16(v.z - __bfloat162float(h2));
    pl1.y = __float2bfloat16(v.w - __bfloat162float(h3));
    ((__nv_bfloat162*)hi)[i * 2 + 0] = ph0;
    ((__nv_bfloat162*)hi)[i * 2 + 1] = ph1;
    ((__nv_bfloat162*)lo)[i * 2 + 0] = pl0;
    ((__nv_bfloat162*)lo)[i * 2 + 1] = pl1;
}

// ---------------- bf16x3 GEMM: C = Ahi*Bhi + Ahi*Blo + Alo*Bhi + bias ----------------
#define BM 128
#define BN 128
#define BK 32
#define A_STRIDE 40
#define B_STRIDE 136
#define A_BYTES (128 * A_STRIDE * 2)
#define B_BYTES (32 * B_STRIDE * 2)
#define STAGE_BYTES (2 * A_BYTES + 2 * B_BYTES)
#define GEMM_SMEM (2 * STAGE_BYTES)

__device__ __forceinline__ void gemm_load_stage(
    unsigned base, int t,
    const __nv_bfloat16* __restrict__ Ahi, const __nv_bfloat16* __restrict__ Alo,
    const __nv_bfloat16* __restrict__ Bhi, const __nv_bfloat16* __restrict__ Blo,
    int brow, int bcol, int k0, int K, int N)
{
    unsigned aHi = base;
    unsigned aLo = base + A_BYTES;
    unsigned bHi = base + 2 * A_BYTES;
    unsigned bLo = bHi + B_BYTES;
#pragma unroll
    for (int i = 0; i < 2; i++) {
        int c = t + i * 256;
        int ar = c >> 2;                // 0..127
        int ak = (c & 3) * 8;           // 0,8,16,24
        size_t ga = (size_t)(brow + ar) * K + k0 + ak;
        unsigned sa = (unsigned)(ar * A_STRIDE + ak) * 2u;
        cp16(aHi + sa, Ahi + ga);
        cp16(aLo + sa, Alo + ga);
        int br = c >> 4;                // 0..31
        int nn = (c & 15) * 8;          // 0..120
        size_t gb = (size_t)(k0 + br) * N + bcol + nn;
        unsigned sb = (unsigned)(br * B_STRIDE + nn) * 2u;
        cp16(bHi + sb, Bhi + gb);
        cp16(bLo + sb, Blo + gb);
    }
    cp_commit();
}

__device__ __forceinline__ void gemm_compute_stage(
    unsigned base, int lane, int wm, int wn, float acc[4][4][4])
{
    unsigned aHi = base;
    unsigned bHi = base + 2 * A_BYTES;
#pragma unroll
    for (int kk = 0; kk < 32; kk += 16) {
        unsigned ah[4][4], al[4][4];
        const int arow = wm * 64 + (lane & 15);
        const int akc = kk + ((lane >> 4) << 3);
#pragma unroll
        for (int mt = 0; mt < 4; mt++) {
            unsigned ad = aHi + (unsigned)((arow + mt * 16) * A_STRIDE + akc) * 2u;
            ldm4(ah[mt], ad);
            ldm4(al[mt], ad + A_BYTES);
        }
        unsigned bh[2][4], bl[2][4];
        const int krow = kk + (lane & 15);
        const int nc0 = wn * 32 + ((lane >> 4) << 3);
#pragma unroll
        for (int np = 0; np < 2; np++) {
            unsigned bd = bHi + (unsigned)(krow * B_STRIDE + nc0 + np * 16) * 2u;
            ldm4t(bh[np], bd);
            ldm4t(bl[np], bd + B_BYTES);
        }
#pragma unroll
        for (int mt = 0; mt < 4; mt++) {
#pragma unroll
            for (int np = 0; np < 2; np++) {
#pragma unroll
                for (int hlf = 0; hlf < 2; hlf++) {
                    float* d = acc[mt][np * 2 + hlf];
                    mma16816(d, ah[mt], &bh[np][hlf * 2]);   // hi*hi
                    mma16816(d, ah[mt], &bl[np][hlf * 2]);   // hi*lo
                    mma16816(d, al[mt], &bh[np][hlf * 2]);   // lo*hi
                }
            }
        }
    }
}

__global__ __launch_bounds__(256) void gemm_bf16x3(
    const __nv_bfloat16* __restrict__ Ahi, const __nv_bfloat16* __restrict__ Alo,
    const __nv_bfloat16* __restrict__ Bhi, const __nv_bfloat16* __restrict__ Blo,
    const float* __restrict__ bias, float* __restrict__ C,
    int M, int N, int K)
{
    extern __shared__ char dynsm[];
    const int t = threadIdx.x;
    const int lane = t & 31;
    const int warp = t >> 5;
    const int wm = warp >> 2;      // 0..1
    const int wn = warp & 3;       // 0..3
    const int brow = blockIdx.y * BM;
    const int bcol = blockIdx.x * BN;

    const unsigned smbase = smem_u32(dynsm);

    float acc[4][4][4];
#pragma unroll
    for (int i = 0; i < 4; i++)
#pragma unroll
        for (int j = 0; j < 4; j++)
#pragma unroll
            for (int k = 0; k < 4; k++) acc[i][j][k] = 0.f;

    const int niter = K / BK;
    gemm_load_stage(smbase, t, Ahi, Alo, Bhi, Blo, brow, bcol, 0, K, N);
    for (int it = 0; it < niter; it++) {
        if (it + 1 < niter) {
            gemm_load_stage(smbase + ((it + 1) & 1) * STAGE_BYTES, t,
                            Ahi, Alo, Bhi, Blo, brow, bcol, (it + 1) * BK, K, N);
            cp_wait_1();
        } else {
            cp_wait_0();
        }
        __syncthreads();
        gemm_compute_stage(smbase + (it & 1) * STAGE_BYTES, lane, wm, wn, acc);
        __syncthreads();
    }

    // epilogue
    const int g = lane >> 2;
    const int t2 = (lane & 3) * 2;
#pragma unroll
    for (int mt = 0; mt < 4; mt++) {
        int row = brow + wm * 64 + mt * 16 + g;
#pragma unroll
        for (int nt = 0; nt < 4; nt++) {
            int col = bcol + wn * 32 + nt * 8 + t2;
            float b0 = bias[col], b1 = bias[col + 1];
            float2 v0 = make_float2(acc[mt][nt][0] + b0, acc[mt][nt][1] + b1);
            float2 v1 = make_float2(acc[mt][nt][2] + b0, acc[mt][nt][3] + b1);
            *(float2*)(C + (size_t)row * N + col) = v0;
            *(float2*)(C + (size_t)(row + 8) * N + col) = v1;
        }
    }
}

// ---------------- rotary + scatter to [B,H,S,HS] ----------------
__global__ __launch_bounds__(256) void rotary_scatter(
    const float* __restrict__ qkv, const int* __restrict__ pos,
    float* __restrict__ Q, float* __restrict__ K, float* __restrict__ V)
{
    int idx = blockIdx.x * 256 + threadIdx.x;
    int d = idx & 127;
    int h = (idx >> 7) & 15;
    int s = (idx >> 11) & (S_ - 1);
    int b = idx >> 22;

    const float* base = qkv + (size_t)(b * S_ + s) * (3 * HID_) + h * (3 * HS_);
    float q = base[d];
    float k = base[HS_ + d];
    float v = base[2 * HS_ + d];

    if (d < RD_) {
        float p = (float)pos[b * S_ + s];
        int i = d & 15;
        float f = p * expf((float)(2 * i) * (-1.0f / (float)RD_) * 9.210340371976184f);
        float c = cosf(f);
        float sn = sinf(f);
        int pd = (d < 16) ? d + 16 : d - 16;
        float sgn = (d < 16) ? -1.f : 1.f;
        float qp = base[pd];
        float kp = base[HS_ + pd];
        q = q * c + sgn * qp * sn;
        k = k * c + sgn * kp * sn;
    }
    size_t oi = ((size_t)(b * H_ + h) * S_ + s) * HS_ + d;
    Q[oi] = q;
    K[oi] = k;
    V[oi] = v;
}

// ---------------- flash attention (causal), fp32, bf16-split output ----------------
#define FA_SMEM_FLOATS (128*68 + 128*68 + 64*128 + 64*64 + 192)
#define FA_SMEM_BYTES  (FA_SMEM_FLOATS * 4)

__global__ __launch_bounds__(256) void flash_attn(
    const float* __restrict__ Q, const float* __restrict__ Kg,
    const float* __restrict__ V, const float* __restrict__ amask,
    __nv_bfloat16* __restrict__ Outhi, __nv_bfloat16* __restrict__ Outlo)
{
    extern __shared__ char dynsm[];
    float* smf = (float*)dynsm;
    float* Qs = smf;
    float* Ks = Qs + 128 * 68;
    float* Vs = Ks + 128 * 68;
    float* Ps = Vs + 64 * 128;
    float* m_s  = Ps + 64 * 64;
    float* l_s  = m_s + 64;
    float* sc_s = l_s + 64;

    const int t = threadIdx.x;
    const int qt = blockIdx.x;
    const int h  = blockIdx.y;
    const int b  = blockIdx.z;
    const int q0 = qt * 64;
    const size_t bh = ((size_t)(b * H_ + h)) * S_ * HS_;

#pragma unroll
    for (int i = 0; i < 8; i++) {
        int f = t + i * 256;
        int r = f >> 5;
        int d = (f & 31) << 2;
        float4 v4 = *(const float4*)(Q + bh + (size_t)(q0 + r) * HS_ + d);
        Qs[(d + 0) * 68 + r] = v4.x;
        Qs[(d + 1) * 68 + r] = v4.y;
        Qs[(d + 2) * 68 + r] = v4.z;
        Qs[(d + 3) * 68 + r] = v4.w;
    }
    if (t < 64) { m_s[t] = -1e30f; l_s[t] = 0.f; }

    float o[8][4];
#pragma unroll
    for (int i = 0; i < 8; i++)
#pragma unroll
        for (int j = 0; j < 4; j++) o[i][j] = 0.f;

    const int rA = (t >> 4) * 4;
    const int cA = (t & 15) * 4;
    const int rB = (t >> 5) * 8;
    const int cB = (t & 31) * 4;

    const float scale = 0.08838834764831845f;

    for (int kt = 0; kt <= qt; kt++) {
        const int k0 = kt * 64;
        __syncthreads();

#pragma unroll
        for (int i = 0; i < 8; i++) {
            int f = t + i * 256;
            int r = f >> 5;
            int d = (f & 31) << 2;
            float4 kv = *(const float4*)(Kg + bh + (size_t)(k0 + r) * HS_ + d);
            Ks[(d + 0) * 68 + r] = kv.x;
            Ks[(d + 1) * 68 + r] = kv.y;
            Ks[(d + 2) * 68 + r] = kv.z;
            Ks[(d + 3) * 68 + r] = kv.w;
            *(float4*)(Vs + r * 128 + d) = *(const float4*)(V + bh + (size_t)(k0 + r) * HS_ + d);
        }
        __syncthreads();

        float s4[4][4];
#pragma unroll
        for (int i = 0; i < 4; i++)
#pragma unroll
            for (int j = 0; j < 4; j++) s4[i][j] = 0.f;

#pragma unroll 4
        for (int d = 0; d < 128; d++) {
            float4 qa = *(float4*)(Qs + d * 68 + rA);
            float4 kb = *(float4*)(Ks + d * 68 + cA);
            float a0 = qa.x, a1 = qa.y, a2 = qa.z, a3 = qa.w;
            float b0 = kb.x, b1 = kb.y, b2 = kb.z, b3 = kb.w;
            s4[0][0] = fmaf(a0, b0, s4[0][0]); s4[0][1] = fmaf(a0, b1, s4[0][1]);
            s4[0][2] = fmaf(a0, b2, s4[0][2]); s4[0][3] = fmaf(a0, b3, s4[0][3]);
            s4[1][0] = fmaf(a1, b0, s4[1][0]); s4[1][1] = fmaf(a1, b1, s4[1][1]);
            s4[1][2] = fmaf(a1, b2, s4[1][2]); s4[1][3] = fmaf(a1, b3, s4[1][3]);
            s4[2][0] = fmaf(a2, b0, s4[2][0]); s4[2][1] = fmaf(a2, b1, s4[2][1]);
            s4[2][2] = fmaf(a2, b2, s4[2][2]); s4[2][3] = fmaf(a2, b3, s4[2][3]);
            s4[3][0] = fmaf(a3, b0, s4[3][0]); s4[3][1] = fmaf(a3, b1, s4[3][1]);
            s4[3][2] = fmaf(a3, b2, s4[3][2]); s4[3][3] = fmaf(a3, b3, s4[3][3]);
        }

        float mold[4], mnew[4], psum[4];
#pragma unroll
        for (int i = 0; i < 4; i++) {
            int qrow = q0 + rA + i;
            float mm = -1e30f;
#pragma unroll
            for (int j = 0; j < 4; j++) {
                int kcol = k0 + cA + j;
                float v = (kcol <= qrow) ? (s4[i][j] * scale + amask[(size_t)b * S_ + kcol]) : -1e30f;
                s4[i][j] = v;
                mm = fmaxf(mm, v);
            }
#pragma unroll
            for (int off = 1; off < 16; off <<= 1)
                mm = fmaxf(mm, __shfl_xor_sync(0xffffffffu, mm, off));
            mold[i] = m_s[rA + i];
            mnew[i] = fmaxf(mold[i], mm);
            float ps = 0.f;
#pragma unroll
            for (int j = 0; j < 4; j++) {
                float p = __expf(s4[i][j] - mnew[i]);
                s4[i][j] = p;
                ps += p;
            }
#pragma unroll
            for (int off = 1; off < 16; off <<= 1)
                ps += __shfl_xor_sync(0xffffffffu, ps, off);
            psum[i] = ps;
        }
        if ((t & 15) == 0) {
#pragma unroll
            for (int i = 0; i < 4; i++) {
                float scl = __expf(mold[i] - mnew[i]);
                sc_s[rA + i] = scl;
                l_s[rA + i] = l_s[rA + i] * scl + psum[i];
                m_s[rA + i] = mnew[i];
            }
        }
#pragma unroll
        for (int i = 0; i < 4; i++)
            *(float4*)(Ps + (rA + i) * 64 + cA) =
                make_float4(s4[i][0], s4[i][1], s4[i][2], s4[i][3]);
        __syncthreads();

#pragma unroll
        for (int i = 0; i < 8; i++) {
            float f = sc_s[rB + i];
            o[i][0] *= f; o[i][1] *= f; o[i][2] *= f; o[i][3] *= f;
        }
#pragma unroll 2
        for (int c = 0; c < 64; c++) {
            float4 vv = *(float4*)(Vs + c * 128 + cB);
#pragma unroll
            for (int i = 0; i < 8; i++) {
                float p = Ps[(rB + i) * 64 + c];
                o[i][0] = fmaf(p, vv.x, o[i][0]);
                o[i][1] = fmaf(p, vv.y, o[i][1]);
                o[i][2] = fmaf(p, vv.z, o[i][2]);
                o[i][3] = fmaf(p, vv.w, o[i][3]);
            }
        }
    }

#pragma unroll
    for (int i = 0; i < 8; i++) {
        float rl = 1.0f / l_s[rB + i];
        float v0 = o[i][0] * rl, v1 = o[i][1] * rl, v2 = o[i][2] * rl, v3 = o[i][3] * rl;
        __nv_bfloat16 h0 = __float2bfloat16(v0);
        __nv_bfloat16 h1 = __float2bfloat16(v1);
        __nv_bfloat16 h2 = __float2bfloat16(v2);
        __nv_bfloat16 h3 = __float2bfloat16(v3);
        __nv_bfloat162 ph0; ph0.x = h0; ph0.y = h1;
        __nv_bfloat162 ph1; ph1.x = h2; ph1.y = h3;
        __nv_bfloat162 pl0, pl1;
        pl0.x = __float2bfloat16(v0 - __bfloat162float(h0));
        pl0.y = __float2bfloat16(v1 - __bfloat162float(h1));
        pl1.x = __float2bfloat16(v2 - __bfloat162float(h2));
        pl1.y = __float2bfloat16(v3 - __bfloat162float(h3));
        size_t oi = ((size_t)(b * S_ + q0 + rB + i)) * HID_ + h * HS_ + cB;
        *(__nv_bfloat162*)(Outhi + oi)     = ph0;
        *(__nv_bfloat162*)(Outhi + oi + 2) = ph1;
        *(__nv_bfloat162*)(Outlo + oi)     = pl0;
        *(__nv_bfloat162*)(Outlo + oi + 2) = pl1;
    }
}

// ---------------- launch ----------------
extern "C" void kernel_launch(void* const* d_in, const int* in_sizes, int n_in,
                              void* d_out, int out_size) {
    const float* hidden = (const float*)d_in[0];
    const float* amask  = (const float*)d_in[1];
    const int*   pos    = (const int*)d_in[2];
    const float* Wqkv   = (const float*)d_in[3];
    const float* bqkv   = (const float*)d_in[4];
    const float* Wd     = (const float*)d_in[5];
    const float* bd     = (const float*)d_in[6];
    float* out = (float*)d_out;

    float *qkv, *Qp, *Kp, *Vp;
    __nv_bfloat16 *Ahi, *Alo, *Wqhi, *Wqlo, *Wdhi, *Wdlo, *Atthi, *Attlo;
    cudaGetSymbolAddress((void**)&qkv, g_qkv);
    cudaGetSymbolAddress((void**)&Qp,  g_Q);
    cudaGetSymbolAddress((void**)&Kp,  g_K);
    cudaGetSymbolAddress((void**)&Vp,  g_V);
    cudaGetSymbolAddress((void**)&Ahi, g_Ahi);
    cudaGetSymbolAddress((void**)&Alo, g_Alo);
    cudaGetSymbolAddress((void**)&Wqhi, g_Wqhi);
    cudaGetSymbolAddress((void**)&Wqlo, g_Wqlo);
    cudaGetSymbolAddress((void**)&Wdhi, g_Wdhi);
    cudaGetSymbolAddress((void**)&Wdlo, g_Wdlo);
    cudaGetSymbolAddress((void**)&Atthi, g_Atthi);
    cudaGetSymbolAddress((void**)&Attlo, g_Attlo);

    cudaFuncSetAttribute(flash_attn, cudaFuncAttributeMaxDynamicSharedMemorySize, FA_SMEM_BYTES);
    cudaFuncSetAttribute(gemm_bf16x3, cudaFuncAttributeMaxDynamicSharedMemorySize, GEMM_SMEM);

    // 0) split inputs/weights into bf16 hi/lo
    split_bf16<<<(B_ * S_ * HID_ / 4 + 255) / 256, 256>>>(hidden, Ahi, Alo, B_ * S_ * HID_ / 4);
    split_bf16<<<(HID_ * 3 * HID_ / 4 + 255) / 256, 256>>>(Wqkv, Wqhi, Wqlo, HID_ * 3 * HID_ / 4);
    split_bf16<<<(HID_ * HID_ / 4 + 255) / 256, 256>>>(Wd, Wdhi, Wdlo, HID_ * HID_ / 4);

    // 1) QKV GEMM (bf16x3 tensor core) + bias
    gemm_bf16x3<<<dim3((3 * HID_) / BN, (B_ * S_) / BM), 256, GEMM_SMEM>>>(
        Ahi, Alo, Wqhi, Wqlo, bqkv, qkv, B_ * S_, 3 * HID_, HID_);

    // 2) rotary + transpose scatter
    rotary_scatter<<<(B_ * S_ * H_ * HS_) / 256, 256>>>(qkv, pos, Qp, Kp, Vp);

    // 3) causal flash attention (writes bf16 hi/lo split directly)
    flash_attn<<<dim3(S_ / 64, H_, B_), 256, FA_SMEM_BYTES>>>(Qp, Kp, Vp, amask, Atthi, Attlo);

    // 4) dense GEMM (bf16x3) + bias
    gemm_bf16x3<<<dim3(HID_ / BN, (B_ * S_) / BM), 256, GEMM_SMEM>>>(
        Atthi, Attlo, Wdhi, Wdlo, bd, out, B_ * S_, HID_, HID_);
}

// round 5
// speedup vs baseline: 2.8171x; 1.5951x over previous
#include <cuda_runtime.h>
#include <cuda_bf16.h>
#include <math.h>
#include <stdint.h>
#include <stddef.h>

#define B_   2
#define S_   2048
#define HID_ 2048
#define H_   16
#define HS_  128
#define RD_  32

// ---------------- scratch (device globals) ----------------
__device__ float g_qkv[(size_t)B_ * S_ * 3 * HID_];     // [4096, 6144] raw qkv

// bf16 split buffers
__device__ __nv_bfloat16 g_Ahi[(size_t)B_ * S_ * HID_];
__device__ __nv_bfloat16 g_Alo[(size_t)B_ * S_ * HID_];
__device__ __nv_bfloat16 g_Wqhi[(size_t)HID_ * 3 * HID_];
__device__ __nv_bfloat16 g_Wqlo[(size_t)HID_ * 3 * HID_];
__device__ __nv_bfloat16 g_Wdhi[(size_t)HID_ * HID_];
__device__ __nv_bfloat16 g_Wdlo[(size_t)HID_ * HID_];
__device__ __nv_bfloat16 g_Atthi[(size_t)B_ * S_ * HID_];
__device__ __nv_bfloat16 g_Attlo[(size_t)B_ * S_ * HID_];

// attention operands, bf16 hi/lo
__device__ __nv_bfloat16 g_Qhi[(size_t)B_ * H_ * S_ * HS_];   // [b,h,s,d]
__device__ __nv_bfloat16 g_Qlo[(size_t)B_ * H_ * S_ * HS_];
__device__ __nv_bfloat16 g_Kthi[(size_t)B_ * H_ * HS_ * S_];  // [b,h,d,s] (transposed)
__device__ __nv_bfloat16 g_Ktlo[(size_t)B_ * H_ * HS_ * S_];
__device__ __nv_bfloat16 g_Vhi[(size_t)B_ * H_ * S_ * HS_];   // [b,h,s,d]
__device__ __nv_bfloat16 g_Vlo[(size_t)B_ * H_ * S_ * HS_];

// ---------------- PTX helpers ----------------
__device__ __forceinline__ unsigned smem_u32(const void* p) {
    return (unsigned)__cvta_generic_to_shared(p);
}
__device__ __forceinline__ void cp16(unsigned s, const void* g) {
    asm volatile("cp.async.cg.shared.global [%0], [%1], 16;" :: "r"(s), "l"(g));
}
__device__ __forceinline__ void cp_commit() {
    asm volatile("cp.async.commit_group;");
}
__device__ __forceinline__ void cp_wait_1() {
    asm volatile("cp.async.wait_group 1;");
}
__device__ __forceinline__ void cp_wait_0() {
    asm volatile("cp.async.wait_group 0;");
}
__device__ __forceinline__ void ldm4(unsigned* r, unsigned a) {
    asm volatile("ldmatrix.sync.aligned.m8n8.x4.shared.b16 {%0,%1,%2,%3}, [%4];"
        : "=r"(r[0]), "=r"(r[1]), "=r"(r[2]), "=r"(r[3]) : "r"(a));
}
__device__ __forceinline__ void ldm4t(unsigned* r, unsigned a) {
    asm volatile("ldmatrix.sync.aligned.m8n8.x4.trans.shared.b16 {%0,%1,%2,%3}, [%4];"
        : "=r"(r[0]), "=r"(r[1]), "=r"(r[2]), "=r"(r[3]) : "r"(a));
}
__device__ __forceinline__ void mma16816(float* d, const unsigned* a, const unsigned* b) {
    asm volatile(
        "mma.sync.aligned.m16n8k16.row.col.f32.bf16.bf16.f32 "
        "{%0,%1,%2,%3},{%4,%5,%6,%7},{%8,%9},{%0,%1,%2,%3};"
        : "+f"(d[0]), "+f"(d[1]), "+f"(d[2]), "+f"(d[3])
        : "r"(a[0]), "r"(a[1]), "r"(a[2]), "r"(a[3]), "r"(b[0]), "r"(b[1]));
}
__device__ __forceinline__ unsigned pack_bf2(float x, float y) {
    __nv_bfloat162 v = __floats2bfloat162_rn(x, y);
    return *reinterpret_cast<unsigned*>(&v);
}

// ---------------- bf16 split conversion ----------------
__global__ __launch_bounds__(256) void split_bf16(
    const float* __restrict__ x, __nv_bfloat16* __restrict__ hi,
    __nv_bfloat16* __restrict__ lo, int n4)
{
    int i = blockIdx.x * 256 + threadIdx.x;
    if (i >= n4) return;
    float4 v = ((const float4*)x)[i];
    __nv_bfloat162 ph0 = __floats2bfloat162_rn(v.x, v.y);
    __nv_bfloat162 ph1 = __floats2bfloat162_rn(v.z, v.w);
    float2 f0 = __bfloat1622float2(ph0);
    float2 f1 = __bfloat1622float2(ph1);
    __nv_bfloat162 pl0 = __floats2bfloat162_rn(v.x - f0.x, v.y - f0.y);
    __nv_bfloat162 pl1 = __floats2bfloat162_rn(v.z - f1.x, v.w - f1.y);
    ((__nv_bfloat162*)hi)[i * 2 + 0] = ph0;
    ((__nv_bfloat162*)hi)[i * 2 + 1] = ph1;
    ((__nv_bfloat162*)lo)[i * 2 + 0] = pl0;
    ((__nv_bfloat162*)lo)[i * 2 + 1] = pl1;
}

// ---------------- bf16x3 GEMM (unchanged from R4) ----------------
#define BM 128
#define BN 128
#define BK 32
#define A_STRIDE 40
#define B_STRIDE 136
#define A_BYTES (128 * A_STRIDE * 2)
#define B_BYTES (32 * B_STRIDE * 2)
#define STAGE_BYTES (2 * A_BYTES + 2 * B_BYTES)
#define GEMM_SMEM (2 * STAGE_BYTES)

__device__ __forceinline__ void gemm_load_stage(
    unsigned base, int t,
    const __nv_bfloat16* __restrict__ Ahi, const __nv_bfloat16* __restrict__ Alo,
    const __nv_bfloat16* __restrict__ Bhi, const __nv_bfloat16* __restrict__ Blo,
    int brow, int bcol, int k0, int K, int N)
{
    unsigned aHi = base;
    unsigned aLo = base + A_BYTES;
    unsigned bHi = base + 2 * A_BYTES;
    unsigned bLo = bHi + B_BYTES;
#pragma unroll
    for (int i = 0; i < 2; i++) {
        int c = t + i * 256;
        int ar = c >> 2;
        int ak = (c & 3) * 8;
        size_t ga = (size_t)(brow + ar) * K + k0 + ak;
        unsigned sa = (unsigned)(ar * A_STRIDE + ak) * 2u;
        cp16(aHi + sa, Ahi + ga);
        cp16(aLo + sa, Alo + ga);
        int br = c >> 4;
        int nn = (c & 15) * 8;
        size_t gb = (size_t)(k0 + br) * N + bcol + nn;
        unsigned sb = (unsigned)(br * B_STRIDE + nn) * 2u;
        cp16(bHi + sb, Bhi + gb);
        cp16(bLo + sb, Blo + gb);
    }
    cp_commit();
}

__device__ __forceinline__ void gemm_compute_stage(
    unsigned base, int lane, int wm, int wn, float acc[4][4][4])
{
    unsigned aHi = base;
    unsigned bHi = base + 2 * A_BYTES;
#pragma unroll
    for (int kk = 0; kk < 32; kk += 16) {
        unsigned ah[4][4], al[4][4];
        const int arow = wm * 64 + (lane & 15);
        const int akc = kk + ((lane >> 4) << 3);
#pragma unroll
        for (int mt = 0; mt < 4; mt++) {
            unsigned ad = aHi + (unsigned)((arow + mt * 16) * A_STRIDE + akc) * 2u;
            ldm4(ah[mt], ad);
            ldm4(al[mt], ad + A_BYTES);
        }
        unsigned bh[2][4], bl[2][4];
        const int krow = kk + (lane & 15);
        const int nc0 = wn * 32 + ((lane >> 4) << 3);
#pragma unroll
        for (int np = 0; np < 2; np++) {
            unsigned bd = bHi + (unsigned)(krow * B_STRIDE + nc0 + np * 16) * 2u;
            ldm4t(bh[np], bd);
            ldm4t(bl[np], bd + B_BYTES);
        }
#pragma unroll
        for (int mt = 0; mt < 4; mt++) {
#pragma unroll
            for (int np = 0; np < 2; np++) {
#pragma unroll
                for (int hlf = 0; hlf < 2; hlf++) {
                    float* d = acc[mt][np * 2 + hlf];
                    mma16816(d, ah[mt], &bh[np][hlf * 2]);
                    mma16816(d, ah[mt], &bl[np][hlf * 2]);
                    mma16816(d, al[mt], &bh[np][hlf * 2]);
                }
            }
        }
    }
}

__global__ __launch_bounds__(256) void gemm_bf16x3(
    const __nv_bfloat16* __restrict__ Ahi, const __nv_bfloat16* __restrict__ Alo,
    const __nv_bfloat16* __restrict__ Bhi, const __nv_bfloat16* __restrict__ Blo,
    const float* __restrict__ bias, float* __restrict__ C,
    int M, int N, int K)
{
    extern __shared__ char dynsm[];
    const int t = threadIdx.x;
    const int lane = t & 31;
    const int warp = t >> 5;
    const int wm = warp >> 2;
    const int wn = warp & 3;
    const int brow = blockIdx.y * BM;
    const int bcol = blockIdx.x * BN;

    const unsigned smbase = smem_u32(dynsm);

    float acc[4][4][4];
#pragma unroll
    for (int i = 0; i < 4; i++)
#pragma unroll
        for (int j = 0; j < 4; j++)
#pragma unroll
            for (int k = 0; k < 4; k++) acc[i][j][k] = 0.f;

    const int niter = K / BK;
    gemm_load_stage(smbase, t, Ahi, Alo, Bhi, Blo, brow, bcol, 0, K, N);
    for (int it = 0; it < niter; it++) {
        if (it + 1 < niter) {
            gemm_load_stage(smbase + ((it + 1) & 1) * STAGE_BYTES, t,
                            Ahi, Alo, Bhi, Blo, brow, bcol, (it + 1) * BK, K, N);
            cp_wait_1();
        } else {
            cp_wait_0();
        }
        __syncthreads();
        gemm_compute_stage(smbase + (it & 1) * STAGE_BYTES, lane, wm, wn, acc);
        __syncthreads();
    }

    const int g = lane >> 2;
    const int t2 = (lane & 3) * 2;
#pragma unroll
    for (int mt = 0; mt < 4; mt++) {
        int row = brow + wm * 64 + mt * 16 + g;
#pragma unroll
        for (int nt = 0; nt < 4; nt++) {
            int col = bcol + wn * 32 + nt * 8 + t2;
            float b0 = bias[col], b1 = bias[col + 1];
            float2 v0 = make_float2(acc[mt][nt][0] + b0, acc[mt][nt][1] + b1);
            float2 v1 = make_float2(acc[mt][nt][2] + b0, acc[mt][nt][3] + b1);
            *(float2*)(C + (size_t)row * N + col) = v0;
            *(float2*)(C + (size_t)(row + 8) * N + col) = v1;
        }
    }
}

// ---------------- rotary + split + scatter (Q,V natural; K transposed) ----------------
#define ROT_SMEM (128 * 133 * 4)

__global__ __launch_bounds__(256) void rotary_split(
    const float* __restrict__ qkv, const int* __restrict__ pos,
    __nv_bfloat16* __restrict__ Qhi, __nv_bfloat16* __restrict__ Qlo,
    __nv_bfloat16* __restrict__ Kthi, __nv_bfloat16* __restrict__ Ktlo,
    __nv_bfloat16* __restrict__ Vhi, __nv_bfloat16* __restrict__ Vlo)
{
    extern __shared__ char dynsm[];
    unsigned* ksm = (unsigned*)dynsm;   // [128 s][133 d] packed (hi,lo)

    const int t = threadIdx.x;
    const int s0 = blockIdx.x * 128;
    const int h = blockIdx.y, b = blockIdx.z;

#pragma unroll 4
    for (int i = 0; i < 64; i++) {
        int idx = t + i * 256;          // 0..16383
        int d = idx & 127;
        int s = idx >> 7;               // 0..127
        const float* base = qkv + (size_t)(b * S_ + s0 + s) * (3 * HID_) + h * (3 * HS_);
        float q = base[d];
        float k = base[HS_ + d];
        float v = base[2 * HS_ + d];

        if (d < RD_) {
            float p = (float)pos[b * S_ + s0 + s];
            int fi = d & 15;
            float f = p * expf((float)(2 * fi) * (-1.0f / (float)RD_) * 9.210340371976184f);
            float c = cosf(f);
            float sn = sinf(f);
            int pd = (d < 16) ? d + 16 : d - 16;
            float sgn = (d < 16) ? -1.f : 1.f;
            float qp = base[pd];
            float kp = base[HS_ + pd];
            q = q * c + sgn * qp * sn;
            k = k * c + sgn * kp * sn;
        }

        size_t oi = ((size_t)(b * H_ + h) * S_ + s0 + s) * HS_ + d;
        __nv_bfloat16 qh = __float2bfloat16(q);
        Qhi[oi] = qh;
        Qlo[oi] = __float2bfloat16(q - __bfloat162float(qh));
        __nv_bfloat16 vh = __float2bfloat16(v);
        Vhi[oi] = vh;
        Vlo[oi] = __float2bfloat16(v - __bfloat162float(vh));

        __nv_bfloat16 kh = __float2bfloat16(k);
        __nv_bfloat16 kl = __float2bfloat16(k - __bfloat162float(kh));
        unsigned pk = (unsigned)__bfloat16_as_ushort(kh) |
                      ((unsigned)__bfloat16_as_ushort(kl) << 16);
        ksm[s * 133 + d] = pk;
    }
    __syncthreads();

#pragma unroll 4
    for (int i = 0; i < 64; i++) {
        int idx = t + i * 256;
        int s = idx & 127;
        int d = idx >> 7;
        unsigned pk = ksm[s * 133 + d];
        size_t ko = ((size_t)(b * H_ + h) * HS_ + d) * S_ + s0 + s;
        Kthi[ko] = __ushort_as_bfloat16((unsigned short)(pk & 0xffffu));
        Ktlo[ko] = __ushort_as_bfloat16((unsigned short)(pk >> 16));
    }
}

// ---------------- tensor-core flash attention (causal, bf16x3) ----------------
#define FQ_STRIDE 136
#define FK_STRIDE 72
#define FV_STRIDE 136
#define FQ_BYTES (128 * FQ_STRIDE * 2)   // 34816
#define FK_BYTES (128 * FK_STRIDE * 2)   // 18432
#define FV_BYTES (64 * FV_STRIDE * 2)    // 17408
#define FSTAGE   (2 * FK_BYTES + 2 * FV_BYTES)   // 71680
#define FA_SMEM  (2 * FQ_BYTES + 2 * FSTAGE)     // 212992

__device__ __forceinline__ void fa_load_kv(
    unsigned base, int t,
    const __nv_bfloat16* __restrict__ Kthi, const __nv_bfloat16* __restrict__ Ktlo,
    const __nv_bfloat16* __restrict__ Vhi,  const __nv_bfloat16* __restrict__ Vlo,
    size_t bhk, size_t bh, int k0)
{
    unsigned kH = base, kL = base + FK_BYTES;
    unsigned vH = base + 2 * FK_BYTES, vL = vH + FV_BYTES;
#pragma unroll
    for (int i = 0; i < 4; i++) {
        int idx = t + i * 256;                 // 0..1023
        int kr = idx >> 3, kc = (idx & 7) * 8; // K: row=d 0..127, col=s 0..56
        size_t gk = bhk + (size_t)kr * S_ + k0 + kc;
        unsigned sk = (unsigned)(kr * FK_STRIDE + kc) * 2u;
        cp16(kH + sk, Kthi + gk);
        cp16(kL + sk, Ktlo + gk);
        int vr = idx >> 4, vc = (idx & 15) * 8; // V: row=s 0..63, col=d
        size_t gv = bh + (size_t)(k0 + vr) * HS_ + vc;
        unsigned sv = (unsigned)(vr * FV_STRIDE + vc) * 2u;
        cp16(vH + sv, Vhi + gv);
        cp16(vL + sv, Vlo + gv);
    }
}

__global__ __launch_bounds__(256) void flash_attn_mma(
    const __nv_bfloat16* __restrict__ Qhi, const __nv_bfloat16* __restrict__ Qlo,
    const __nv_bfloat16* __restrict__ Kthi, const __nv_bfloat16* __restrict__ Ktlo,
    const __nv_bfloat16* __restrict__ Vhi,  const __nv_bfloat16* __restrict__ Vlo,
    const float* __restrict__ amask,
    __nv_bfloat16* __restrict__ Outhi, __nv_bfloat16* __restrict__ Outlo)
{
    extern __shared__ char dynsm[];
    const unsigned smb = smem_u32(dynsm);
    const unsigned sQh = smb;                  // Qlo = sQh + FQ_BYTES

    const int t = threadIdx.x, lane = t & 31, w = t >> 5;
    const int qt = gridDim.x - 1 - blockIdx.x;   // heavy blocks first
    const int q0 = qt * 128;
    const int h = blockIdx.y, b = blockIdx.z;
    const size_t bh  = (size_t)(b * H_ + h) * S_ * HS_;
    const size_t bhk = bh;   // same extent, d-major indexing

    // load Q tile (hi+lo) + stage 0, one commit group
#pragma unroll
    for (int i = 0; i < 8; i++) {
        int idx = t + i * 256;                // 0..2047
        int r = idx >> 4, c = (idx & 15) * 8;
        size_t g = bh + (size_t)(q0 + r) * HS_ + c;
        unsigned so = (unsigned)(r * FQ_STRIDE + c) * 2u;
        cp16(sQh + so, Qhi + g);
        cp16(sQh + FQ_BYTES + so, Qlo + g);
    }
    fa_load_kv(smb + 2 * FQ_BYTES, t, Kthi, Ktlo, Vhi, Vlo, bhk, bh, 0);
    cp_commit();

    float Oa[16][4];
#pragma unroll
    for (int i = 0; i < 16; i++)
#pragma unroll
        for (int j = 0; j < 4; j++) Oa[i][j] = 0.f;

    float m0 = -1e30f, m1 = -1e30f, l0 = 0.f, l1 = 0.f;
    const int nkt = 2 * (qt + 1);
    const float scale = 0.08838834764831845f;   // 1/sqrt(128)
    const int qrow0 = q0 + w * 16 + (lane >> 2);
    const int col_t = 2 * (lane & 3);

    for (int kt = 0; kt < nkt; kt++) {
        const int k0 = kt * 64;
        const unsigned stg = smb + 2 * FQ_BYTES + (kt & 1) * FSTAGE;
        if (kt + 1 < nkt) {
            fa_load_kv(smb + 2 * FQ_BYTES + ((kt + 1) & 1) * FSTAGE, t,
                       Kthi, Ktlo, Vhi, Vlo, bhk, bh, (kt + 1) * 64);
            cp_commit();
            cp_wait_1();
        } else {
            cp_wait_0();
        }
        __syncthreads();

        // ---- S = Q K^T (bf16x3) ----
        float Sa[8][4];
#pragma unroll
        for (int i = 0; i < 8; i++)
#pragma unroll
            for (int j = 0; j < 4; j++) Sa[i][j] = 0.f;

#pragma unroll
        for (int kk = 0; kk < 8; kk++) {
            unsigned ah[4], al[4];
            unsigned qa = sQh + (unsigned)((w * 16 + (lane & 15)) * FQ_STRIDE
                                           + kk * 16 + ((lane >> 4) << 3)) * 2u;
            ldm4(ah, qa);
            ldm4(al, qa + FQ_BYTES);
#pragma unroll
            for (int nb = 0; nb < 4; nb++) {
                unsigned kh[4], kl[4];
                unsigned ka = stg + (unsigned)((kk * 16 + (lane & 15)) * FK_STRIDE
                                               + nb * 16 + ((lane >> 4) << 3)) * 2u;
                ldm4t(kh, ka);
                ldm4t(kl, ka + FK_BYTES);
#pragma unroll
                for (int hf = 0; hf < 2; hf++) {
                    mma16816(Sa[nb * 2 + hf], ah, &kh[hf * 2]);
                    mma16816(Sa[nb * 2 + hf], ah, &kl[hf * 2]);
                    mma16816(Sa[nb * 2 + hf], al, &kh[hf * 2]);
                }
            }
        }

        // ---- softmax (online) ----
        const bool needmask = (k0 + 63 > q0 + w * 16);
        float mc0 = -1e30f, mc1 = -1e30f;
#pragma unroll
        for (int j = 0; j < 8; j++) {
            int cb = k0 + j * 8 + col_t;
            float a0 = amask[(size_t)b * S_ + cb];
            float a1 = amask[(size_t)b * S_ + cb + 1];
            Sa[j][0] = Sa[j][0] * scale + a0;
            Sa[j][1] = Sa[j][1] * scale + a1;
            Sa[j][2] = Sa[j][2] * scale + a0;
            Sa[j][3] = Sa[j][3] * scale + a1;
            if (needmask) {
                if (cb > qrow0)         Sa[j][0] = -1e30f;
                if (cb + 1 > qrow0)     Sa[j][1] = -1e30f;
                if (cb > qrow0 + 8)     Sa[j][2] = -1e30f;
                if (cb + 1 > qrow0 + 8) Sa[j][3] = -1e30f;
            }
            mc0 = fmaxf(mc0, fmaxf(Sa[j][0], Sa[j][1]));
            mc1 = fmaxf(mc1, fmaxf(Sa[j][2], Sa[j][3]));
        }
        mc0 = fmaxf(mc0, __shfl_xor_sync(0xffffffffu, mc0, 1));
        mc0 = fmaxf(mc0, __shfl_xor_sync(0xffffffffu, mc0, 2));
        mc1 = fmaxf(mc1, __shfl_xor_sync(0xffffffffu, mc1, 1));
        mc1 = fmaxf(mc1, __shfl_xor_sync(0xffffffffu, mc1, 2));

        float mn0 = fmaxf(m0, mc0), mn1 = fmaxf(m1, mc1);
        float sf0 = __expf(m0 - mn0), sf1 = __expf(m1 - mn1);
        m0 = mn0; m1 = mn1;

        float ps0 = 0.f, ps1 = 0.f;
        unsigned phi[4][4], plo[4][4];
#pragma unroll
        for (int j = 0; j < 8; j++) {
            float p0 = __expf(Sa[j][0] - mn0);
            float p1 = __expf(Sa[j][1] - mn0);
            float p2 = __expf(Sa[j][2] - mn1);
            float p3 = __expf(Sa[j][3] - mn1);
            ps0 += p0 + p1;
            ps1 += p2 + p3;
            __nv_bfloat162 h01 = __floats2bfloat162_rn(p0, p1);
            __nv_bfloat162 h23 = __floats2bfloat162_rn(p2, p3);
            float2 f01 = __bfloat1622float2(h01);
            float2 f23 = __bfloat1622float2(h23);
            __nv_bfloat162 l01 = __floats2bfloat162_rn(p0 - f01.x, p1 - f01.y);
            __nv_bfloat162 l23 = __floats2bfloat162_rn(p2 - f23.x, p3 - f23.y);
            int kf = j >> 1, q = (j & 1) * 2;
            phi[kf][q + 0] = *reinterpret_cast<unsigned*>(&h01);
            phi[kf][q + 1] = *reinterpret_cast<unsigned*>(&h23);
            plo[kf][q + 0] = *reinterpret_cast<unsigned*>(&l01);
            plo[kf][q + 1] = *reinterpret_cast<unsigned*>(&l23);
        }
        ps0 += __shfl_xor_sync(0xffffffffu, ps0, 1);
        ps0 += __shfl_xor_sync(0xffffffffu, ps0, 2);
        ps1 += __shfl_xor_sync(0xffffffffu, ps1, 1);
        ps1 += __shfl_xor_sync(0xffffffffu, ps1, 2);
        l0 = l0 * sf0 + ps0;
        l1 = l1 * sf1 + ps1;

        // rescale O
#pragma unroll
        for (int nb = 0; nb < 16; nb++) {
            Oa[nb][0] *= sf0; Oa[nb][1] *= sf0;
            Oa[nb][2] *= sf1; Oa[nb][3] *= sf1;
        }

        // ---- O += P V (bf16x3) ----
        const unsigned vHb = stg + 2 * FK_BYTES;
#pragma unroll
        for (int kf = 0; kf < 4; kf++) {
#pragma unroll
            for (int nb = 0; nb < 8; nb++) {
                unsigned vh[4], vl[4];
                unsigned va = vHb + (unsigned)((kf * 16 + (lane & 15)) * FV_STRIDE
                                               + nb * 16 + ((lane >> 4) << 3)) * 2u;
                ldm4t(vh, va);
                ldm4t(vl, va + FV_BYTES);
#pragma unroll
                for (int hf = 0; hf < 2; hf++) {
                    mma16816(Oa[nb * 2 + hf], phi[kf], &vh[hf * 2]);
                    mma16816(Oa[nb * 2 + hf], phi[kf], &vl[hf * 2]);
                    mma16816(Oa[nb * 2 + hf], plo[kf], &vh[hf * 2]);
                }
            }
        }
        __syncthreads();
    }

    // epilogue: normalize, split hi/lo, store [b,s,h*HS]
    float rl0 = 1.0f / l0, rl1 = 1.0f / l1;
#pragma unroll
    for (int nb = 0; nb < 16; nb++) {
        int c = nb * 8 + col_t;
        float v0 = Oa[nb][0] * rl0, v1 = Oa[nb][1] * rl0;
        float v2 = Oa[nb][2] * rl1, v3 = Oa[nb][3] * rl1;
        __nv_bfloat162 h01 = __floats2bfloat162_rn(v0, v1);
        __nv_bfloat162 h23 = __floats2bfloat162_rn(v2, v3);
        float2 f01 = __bfloat1622float2(h01);
        float2 f23 = __bfloat1622float2(h23);
        __nv_bfloat162 l01 = __floats2bfloat162_rn(v0 - f01.x, v1 - f01.y);
        __nv_bfloat162 l23 = __floats2bfloat162_rn(v2 - f23.x, v3 - f23.y);
        size_t o0 = (size_t)(b * S_ + qrow0) * HID_ + h * HS_ + c;
        size_t o1 = o0 + (size_t)8 * HID_;
        *reinterpret_cast<__nv_bfloat162*>(Outhi + o0) = h01;
        *reinterpret_cast<__nv_bfloat162*>(Outhi + o1) = h23;
        *reinterpret_cast<__nv_bfloat162*>(Outlo + o0) = l01;
        *reinterpret_cast<__nv_bfloat162*>(Outlo + o1) = l23;
    }
}

// ---------------- launch ----------------
extern "C" void kernel_launch(void* const* d_in, const int* in_sizes, int n_in,
                              void* d_out, int out_size) {
    const float* hidden = (const float*)d_in[0];
    const float* amask  = (const float*)d_in[1];
    const int*   pos    = (const int*)d_in[2];
    const float* Wqkv   = (const float*)d_in[3];
    const float* bqkv   = (const float*)d_in[4];
    const float* Wd     = (const float*)d_in[5];
    const float* bd     = (const float*)d_in[6];
    float* out = (float*)d_out;

    float* qkv;
    __nv_bfloat16 *Ahi, *Alo, *Wqhi, *Wqlo, *Wdhi, *Wdlo, *Atthi, *Attlo;
    __nv_bfloat16 *Qhi, *Qlo, *Kthi, *Ktlo, *Vhi, *Vlo;
    cudaGetSymbolAddress((void**)&qkv, g_qkv);
    cudaGetSymbolAddress((void**)&Ahi, g_Ahi);
    cudaGetSymbolAddress((void**)&Alo, g_Alo);
    cudaGetSymbolAddress((void**)&Wqhi, g_Wqhi);
    cudaGetSymbolAddress((void**)&Wqlo, g_Wqlo);
    cudaGetSymbolAddress((void**)&Wdhi, g_Wdhi);
    cudaGetSymbolAddress((void**)&Wdlo, g_Wdlo);
    cudaGetSymbolAddress((void**)&Atthi, g_Atthi);
    cudaGetSymbolAddress((void**)&Attlo, g_Attlo);
    cudaGetSymbolAddress((void**)&Qhi, g_Qhi);
    cudaGetSymbolAddress((void**)&Qlo, g_Qlo);
    cudaGetSymbolAddress((void**)&Kthi, g_Kthi);
    cudaGetSymbolAddress((void**)&Ktlo, g_Ktlo);
    cudaGetSymbolAddress((void**)&Vhi, g_Vhi);
    cudaGetSymbolAddress((void**)&Vlo, g_Vlo);

    cudaFuncSetAttribute(gemm_bf16x3, cudaFuncAttributeMaxDynamicSharedMemorySize, GEMM_SMEM);
    cudaFuncSetAttribute(rotary_split, cudaFuncAttributeMaxDynamicSharedMemorySize, ROT_SMEM);
    cudaFuncSetAttribute(flash_attn_mma, cudaFuncAttributeMaxDynamicSharedMemorySize, FA_SMEM);

    // 0) split inputs/weights into bf16 hi/lo
    split_bf16<<<(B_ * S_ * HID_ / 4 + 255) / 256, 256>>>(hidden, Ahi, Alo, B_ * S_ * HID_ / 4);
    split_bf16<<<(HID_ * 3 * HID_ / 4 + 255) / 256, 256>>>(Wqkv, Wqhi, Wqlo, HID_ * 3 * HID_ / 4);
    split_bf16<<<(HID_ * HID_ / 4 + 255) / 256, 256>>>(Wd, Wdhi, Wdlo, HID_ * HID_ / 4);

    // 1) QKV GEMM (bf16x3 tensor core) + bias
    gemm_bf16x3<<<dim3((3 * HID_) / BN, (B_ * S_) / BM), 256, GEMM_SMEM>>>(
        Ahi, Alo, Wqhi, Wqlo, bqkv, qkv, B_ * S_, 3 * HID_, HID_);

    // 2) rotary + hi/lo split + K transpose
    rotary_split<<<dim3(S_ / 128, H_, B_), 256, ROT_SMEM>>>(
        qkv, pos, Qhi, Qlo, Kthi, Ktlo, Vhi, Vlo);

    // 3) tensor-core causal flash attention
    flash_attn_mma<<<dim3(S_ / 128, H_, B_), 256, FA_SMEM>>>(
        Qhi, Qlo, Kthi, Ktlo, Vhi, Vlo, amask, Atthi, Attlo);

    // 4) dense GEMM (bf16x3) + bias
    gemm_bf16x3<<<dim3(HID_ / BN, (B_ * S_) / BM), 256, GEMM_SMEM>>>(
        Atthi, Attlo, Wdhi, Wdlo, bd, out, B_ * S_, HID_, HID_);
}